// round 3
// baseline (speedup 1.0000x reference)
#include <cuda_runtime.h>

#define NN 50000
#define KD 128      // input dim of both layers (HID == IN_C == 128)
#define H1 128
#define H2 64
#define NE 800000

// ---------------- scratch (device globals; float4 => 16B alignment) --------
__device__ float g_deg[NN];
__device__ float g_dinv[NN];
__device__ float4 g_hs1[(size_t)NN * H1 / 4];   // (x@W1)*dinv[row]
__device__ float4 g_acc1[(size_t)NN * H1 / 4];  // scatter accumulator layer 1
__device__ float4 g_x2[(size_t)NN * H1 / 4];    // relu output -> layer2 input
__device__ float4 g_hs2[(size_t)NN * H2 / 4];
__device__ float4 g_acc2[(size_t)NN * H2 / 4];

// ---------------- degree / normalization ----------------------------------
__global__ void k_init_deg() {
    int i = blockIdx.x * blockDim.x + threadIdx.x;
    if (i < NN) g_deg[i] = 1.0f;   // self loop
}

__global__ void k_count_deg(const int* __restrict__ dst) {
    int e = blockIdx.x * blockDim.x + threadIdx.x;
    if (e < NE) atomicAdd(&g_deg[dst[e]], 1.0f);
}

__global__ void k_dinv() {
    int i = blockIdx.x * blockDim.x + threadIdx.x;
    if (i < NN) g_dinv[i] = rsqrtf(g_deg[i]);
}

// ---------------- fused GEMM + dinv scale + self-loop init ----------------
// C[i][j] = (sum_k A[i][k] * W[k][j]) * dinv[i]   -> hs and acc (acc = self loop)
// Block: 256 threads, 64 rows x NC cols, full K=128 in one pass.
template <int NC>
__device__ __forceinline__ void gemm_body(const float* __restrict__ A,
                                          const float* __restrict__ W,
                                          float4* __restrict__ hs,
                                          float4* __restrict__ acc)
{
    extern __shared__ float smem[];
    float (*Ws)[NC + 4] = (float (*)[NC + 4])smem;
    float (*As)[KD + 4] = (float (*)[KD + 4])(smem + (size_t)KD * (NC + 4));

    const int tid  = threadIdx.x;
    const int row0 = blockIdx.x * 64;

    // load W (KD x NC) into smem
    for (int i = tid * 4; i < KD * NC; i += 256 * 4) {
        int r = i / NC, c = i % NC;
        float4 v = *(const float4*)(W + (size_t)r * NC + c);
        Ws[r][c] = v.x; Ws[r][c + 1] = v.y; Ws[r][c + 2] = v.z; Ws[r][c + 3] = v.w;
    }
    // load A tile (64 x KD) into smem, zero-pad OOB rows
    for (int i = tid * 4; i < 64 * KD; i += 256 * 4) {
        int r = i >> 7, c = i & (KD - 1);
        int gr = row0 + r;
        float4 v = make_float4(0.f, 0.f, 0.f, 0.f);
        if (gr < NN) v = *(const float4*)(A + (size_t)gr * KD + c);
        As[r][c] = v.x; As[r][c + 1] = v.y; As[r][c + 2] = v.z; As[r][c + 3] = v.w;
    }
    __syncthreads();

    constexpr int TN = NC / 16;          // 8 for NC=128, 4 for NC=64
    const int tx = tid & 15, ty = tid >> 4;
    const int rb = ty * 4, cb = tx * TN;

    float accv[4][TN];
#pragma unroll
    for (int i = 0; i < 4; i++)
#pragma unroll
        for (int j = 0; j < TN; j++) accv[i][j] = 0.f;

#pragma unroll 4
    for (int k = 0; k < KD; k++) {
        float a0 = As[rb][k], a1 = As[rb + 1][k], a2 = As[rb + 2][k], a3 = As[rb + 3][k];
        float b[TN];
#pragma unroll
        for (int j = 0; j < TN; j++) b[j] = Ws[k][cb + j];
#pragma unroll
        for (int j = 0; j < TN; j++) {
            accv[0][j] += a0 * b[j];
            accv[1][j] += a1 * b[j];
            accv[2][j] += a2 * b[j];
            accv[3][j] += a3 * b[j];
        }
    }

#pragma unroll
    for (int i = 0; i < 4; i++) {
        int gr = row0 + rb + i;
        if (gr >= NN) continue;
        float d = g_dinv[gr];
        size_t base4 = ((size_t)gr * NC + cb) >> 2;   // float4 index
#pragma unroll
        for (int j0 = 0; j0 < TN; j0 += 4) {
            float4 v = make_float4(accv[i][j0 + 0] * d, accv[i][j0 + 1] * d,
                                   accv[i][j0 + 2] * d, accv[i][j0 + 3] * d);
            hs[base4 + (j0 >> 2)]  = v;
            acc[base4 + (j0 >> 2)] = v;   // self-loop contribution
        }
    }
}

__global__ void __launch_bounds__(256) k_gemm1(const float* __restrict__ x,
                                               const float* __restrict__ W1) {
    gemm_body<H1>(x, W1, g_hs1, g_acc1);
}
__global__ void __launch_bounds__(256) k_gemm2(const float* __restrict__ W2) {
    gemm_body<H2>((const float*)g_x2, W2, g_hs2, g_acc2);
}

// ---------------- edge scatter: acc[dst] += hs[src] ------------------------
// 128 channels: one warp per edge, each lane handles one float4 (16B).
__global__ void k_scatter1(const int* __restrict__ src,
                           const int* __restrict__ dst)
{
    int w = (blockIdx.x * blockDim.x + threadIdx.x) >> 5;
    if (w >= NE) return;
    int lane = threadIdx.x & 31;
    int s = src[w];
    int d = dst[w];
    float4 v = g_hs1[(size_t)s * (H1 / 4) + lane];
    atomicAdd(&g_acc1[(size_t)d * (H1 / 4) + lane], v);
}

// 64 channels: 16 threads per edge (2 edges per warp), each a float4.
__global__ void k_scatter2(const int* __restrict__ src,
                           const int* __restrict__ dst)
{
    int t = blockIdx.x * blockDim.x + threadIdx.x;
    int e = t >> 4;
    if (e >= NE) return;
    int l = t & 15;
    int s = src[e];
    int d = dst[e];
    float4 v = g_hs2[(size_t)s * (H2 / 4) + l];
    atomicAdd(&g_acc2[(size_t)d * (H2 / 4) + l], v);
}

// ---------------- epilogues ------------------------------------------------
__global__ void k_finish1(const float* __restrict__ b1) {
    int i = blockIdx.x * blockDim.x + threadIdx.x;   // over NN*H1/4 float4s
    if (i >= NN * (H1 / 4)) return;
    int row = i / (H1 / 4);
    int c   = (i % (H1 / 4)) * 4;
    float d = g_dinv[row];
    float4 v = g_acc1[i];
    float4 b = *(const float4*)(b1 + c);
    v.x = fmaxf(fmaf(v.x, d, b.x), 0.f);
    v.y = fmaxf(fmaf(v.y, d, b.y), 0.f);
    v.z = fmaxf(fmaf(v.z, d, b.z), 0.f);
    v.w = fmaxf(fmaf(v.w, d, b.w), 0.f);
    g_x2[i] = v;
}

__global__ void k_finish2(const float* __restrict__ b2, float* __restrict__ out) {
    int i = blockIdx.x * blockDim.x + threadIdx.x;   // over NN*H2/4 float4s
    if (i >= NN * (H2 / 4)) return;
    int row = i / (H2 / 4);
    int c   = (i % (H2 / 4)) * 4;
    float d = g_dinv[row];
    float4 v = g_acc2[i];
    float4 b = *(const float4*)(b2 + c);
    v.x = fmaf(v.x, d, b.x);
    v.y = fmaf(v.y, d, b.y);
    v.z = fmaf(v.z, d, b.z);
    v.w = fmaf(v.w, d, b.w);
    *(float4*)(out + (size_t)row * H2 + c) = v;
}

// ---------------- launch ----------------------------------------------------
extern "C" void kernel_launch(void* const* d_in, const int* in_sizes, int n_in,
                              void* d_out, int out_size)
{
    const float* x  = (const float*)d_in[0];
    const int*   ei = (const int*)d_in[1];    // int32: JAX default (x64 disabled)
    const float* W1 = (const float*)d_in[2];
    const float* b1 = (const float*)d_in[3];
    const float* W2 = (const float*)d_in[4];
    const float* b2 = (const float*)d_in[5];
    float* out = (float*)d_out;

    const int* src = ei;        // edge_index[0]
    const int* dst = ei + NE;   // edge_index[1]

    const int SMEM1 = (KD * (H1 + 4) + 64 * (KD + 4)) * (int)sizeof(float); // ~99 KB
    const int SMEM2 = (KD * (H2 + 4) + 64 * (KD + 4)) * (int)sizeof(float); // ~67 KB
    cudaFuncSetAttribute(k_gemm1, cudaFuncAttributeMaxDynamicSharedMemorySize, SMEM1);
    cudaFuncSetAttribute(k_gemm2, cudaFuncAttributeMaxDynamicSharedMemorySize, SMEM2);

    k_init_deg<<<(NN + 255) / 256, 256>>>();
    k_count_deg<<<(NE + 255) / 256, 256>>>(dst);
    k_dinv<<<(NN + 255) / 256, 256>>>();

    k_gemm1<<<(NN + 63) / 64, 256, SMEM1>>>(x, W1);
    k_scatter1<<<(int)(((size_t)NE * 32 + 255) / 256), 256>>>(src, dst);
    k_finish1<<<(NN * (H1 / 4) + 255) / 256, 256>>>(b1);

    k_gemm2<<<(NN + 63) / 64, 256, SMEM2>>>(W2);
    k_scatter2<<<(int)(((size_t)NE * 16 + 255) / 256), 256>>>(src, dst);
    k_finish2<<<(NN * (H2 / 4) + 255) / 256, 256>>>(b2, out);
}